// round 1
// baseline (speedup 1.0000x reference)
#include <cuda_runtime.h>
#include <math.h>

// ---------------------------------------------------------------------------
// Problem constants (fixed by setup_inputs)
// ---------------------------------------------------------------------------
#define BATCH      8192
#define H1_ELEMS   (8 * 14 * 14)   // 1568
#define FLAT_ELEMS (16 * 7 * 7)    // 784

// ---------------------------------------------------------------------------
// Scratch (static __device__ globals; allocation APIs are forbidden)
// ---------------------------------------------------------------------------
__device__ float g_h1[BATCH * H1_ELEMS];     // conv1 output   [B,8,14,14]
__device__ float g_flat[BATCH * FLAT_ELEMS]; // conv2 output   [B,784]
__device__ float g_feat[BATCH * 4];          // fc2 output     [B,4]
__device__ float g_wT[784 * 64];             // fc1_w transposed
__device__ float g_scsh[8];                  // [scale0..3, shift0..3]

// ---------------------------------------------------------------------------
// K0: transpose fc1_w [64,784] -> g_wT [784,64]
// ---------------------------------------------------------------------------
__global__ void k_transpose_fc1(const float* __restrict__ w) {
    int i = blockIdx.x * 256 + threadIdx.x;
    if (i < 64 * 784) {
        int j = i / 784, k = i % 784;
        g_wT[k * 64 + j] = w[i];
    }
}

// ---------------------------------------------------------------------------
// K1: conv1 (1->8, 3x3 SAME on 28x28) + relu + maxpool2 -> [B,8,14,14]
// One block per sample.
// ---------------------------------------------------------------------------
__global__ void k_conv1(const float* __restrict__ x,
                        const float* __restrict__ w,
                        const float* __restrict__ bias) {
    __shared__ float sx[784];
    __shared__ float sw[72];
    __shared__ float sb[8];
    int b = blockIdx.x, tid = threadIdx.x;
    for (int i = tid; i < 784; i += 256) sx[i] = x[b * 784 + i];
    if (tid < 72) sw[tid] = w[tid];
    if (tid < 8)  sb[tid] = bias[tid];
    __syncthreads();

    for (int idx = tid; idx < H1_ELEMS; idx += 256) {
        int o = idx / 196;
        int r = idx % 196;
        int y2 = r / 14, x2 = r % 14;
        const float* wo = &sw[o * 9];
        float m = -1e30f;
        #pragma unroll
        for (int iy = 0; iy < 2; iy++) {
            #pragma unroll
            for (int ix = 0; ix < 2; ix++) {
                int y = y2 * 2 + iy, xx = x2 * 2 + ix;
                float acc = sb[o];
                #pragma unroll
                for (int dy = 0; dy < 3; dy++) {
                    int yy = y + dy - 1;
                    if (yy < 0 || yy >= 28) continue;
                    #pragma unroll
                    for (int dx = 0; dx < 3; dx++) {
                        int xc = xx + dx - 1;
                        if (xc < 0 || xc >= 28) continue;
                        acc = fmaf(sx[yy * 28 + xc], wo[dy * 3 + dx], acc);
                    }
                }
                acc = fmaxf(acc, 0.0f);
                m = fmaxf(m, acc);
            }
        }
        g_h1[b * H1_ELEMS + idx] = m;
    }
}

// ---------------------------------------------------------------------------
// K2: conv2 (8->16, 3x3 SAME on 14x14) + relu + maxpool2 -> [B,784] flat
// One block per sample; entire per-sample input + weights in SMEM.
// ---------------------------------------------------------------------------
__global__ void k_conv2(const float* __restrict__ w,
                        const float* __restrict__ bias) {
    __shared__ float sh[H1_ELEMS];   // 1568
    __shared__ float sw[16 * 8 * 9]; // 1152
    __shared__ float sb[16];
    int b = blockIdx.x, tid = threadIdx.x;
    for (int i = tid; i < H1_ELEMS; i += 256) sh[i] = g_h1[b * H1_ELEMS + i];
    for (int i = tid; i < 1152; i += 256) sw[i] = w[i];
    if (tid < 16) sb[tid] = bias[tid];
    __syncthreads();

    for (int idx = tid; idx < FLAT_ELEMS; idx += 256) {
        int o = idx / 49;
        int r = idx % 49;
        int y2 = r / 7, x2 = r % 7;
        const float* wo = &sw[o * 72];
        float m = -1e30f;
        #pragma unroll
        for (int iy = 0; iy < 2; iy++) {
            #pragma unroll
            for (int ix = 0; ix < 2; ix++) {
                int y = y2 * 2 + iy, xx = x2 * 2 + ix;
                float acc = sb[o];
                #pragma unroll
                for (int dy = 0; dy < 3; dy++) {
                    int yy = y + dy - 1;
                    if (yy < 0 || yy >= 14) continue;
                    #pragma unroll
                    for (int dx = 0; dx < 3; dx++) {
                        int xc = xx + dx - 1;
                        if (xc < 0 || xc >= 14) continue;
                        const float* hp = &sh[yy * 14 + xc];
                        const float* wp = &wo[dy * 3 + dx];
                        #pragma unroll
                        for (int ic = 0; ic < 8; ic++)
                            acc = fmaf(hp[ic * 196], wp[ic * 9], acc);
                    }
                }
                acc = fmaxf(acc, 0.0f);
                m = fmaxf(m, acc);
            }
        }
        g_flat[b * FLAT_ELEMS + idx] = m;
    }
}

// ---------------------------------------------------------------------------
// K3: FC1 (784->64, relu) + FC2 (64->4) for 8 samples per block.
// 256 threads: j = tid&63 (output neuron), sg = tid>>6 (sample pair).
// ---------------------------------------------------------------------------
__global__ void k_fc(const float* __restrict__ fc1_b,
                     const float* __restrict__ fc2_w,
                     const float* __restrict__ fc2_b) {
    __shared__ float sf[8 * 784];  // 25 KB
    __shared__ float shh[8 * 64];  // 2 KB
    int s0 = blockIdx.x * 8;
    int tid = threadIdx.x;
    for (int i = tid; i < 8 * 784; i += 256) sf[i] = g_flat[s0 * 784 + i];
    __syncthreads();

    int j = tid & 63;
    int sg = tid >> 6;               // 0..3, each handles 2 samples
    const float* f0 = &sf[(2 * sg) * 784];
    const float* f1 = f0 + 784;
    float a0 = 0.f, a1 = 0.f;
    #pragma unroll 8
    for (int k = 0; k < 784; k++) {
        float wv = g_wT[k * 64 + j];
        a0 = fmaf(wv, f0[k], a0);
        a1 = fmaf(wv, f1[k], a1);
    }
    float bb = fc1_b[j];
    shh[(2 * sg) * 64 + j]     = fmaxf(a0 + bb, 0.0f);
    shh[(2 * sg + 1) * 64 + j] = fmaxf(a1 + bb, 0.0f);
    __syncthreads();

    if (tid < 32) {
        int s = tid >> 2, c = tid & 3;
        float acc = fc2_b[c];
        const float* hw = &shh[s * 64];
        const float* wc = &fc2_w[c * 64];
        #pragma unroll
        for (int jj = 0; jj < 64; jj++) acc = fmaf(hw[jj], wc[jj], acc);
        g_feat[(s0 + s) * 4 + c] = acc;
    }
}

// ---------------------------------------------------------------------------
// K4: batch mean/var over feat[:,c], c=0..3 -> scale/shift
// ---------------------------------------------------------------------------
__global__ void k_stats(const float* __restrict__ bn_g,
                        const float* __restrict__ bn_b) {
    __shared__ double ssum[256];
    __shared__ double ssq[256];
    int tid = threadIdx.x;
    int c = tid & 3;
    double sum = 0.0, sq = 0.0;
    for (int s = tid >> 2; s < BATCH; s += 64) {
        double v = (double)g_feat[s * 4 + c];
        sum += v;
        sq += v * v;
    }
    ssum[tid] = sum;
    ssq[tid] = sq;
    __syncthreads();
    for (int off = 128; off >= 4; off >>= 1) {
        if (tid < off) {
            ssum[tid] += ssum[tid + off];
            ssq[tid]  += ssq[tid + off];
        }
        __syncthreads();
    }
    if (tid < 4) {
        double m = ssum[tid] / (double)BATCH;
        double var = ssq[tid] / (double)BATCH - m * m;
        float scale = (float)((double)bn_g[tid] / sqrt(var + 1e-5));
        float shift = bn_b[tid] - (float)m * scale;
        g_scsh[tid] = scale;
        g_scsh[4 + tid] = shift;
    }
}

// ---------------------------------------------------------------------------
// K5: quantum state-vector sim + PauliZ measurement.
// One thread per sample; 16 complex amps in registers.
// Wire w corresponds to bit (3-w): stride STR = 8 >> w.
// ---------------------------------------------------------------------------
template <int STR>
__device__ __forceinline__ void rot_rx(float* sr, float* si, float c, float s) {
    #pragma unroll
    for (int k = 0; k < 16; k++) {
        if (k & STR) continue;
        int k1 = k | STR;
        float ar0 = sr[k], ai0 = si[k], ar1 = sr[k1], ai1 = si[k1];
        // U = [[c, -i s],[-i s, c]]
        sr[k]  = c * ar0 + s * ai1;
        si[k]  = c * ai0 - s * ar1;
        sr[k1] = s * ai0 + c * ar1;
        si[k1] = -s * ar0 + c * ai1;
    }
}

template <int STR>
__device__ __forceinline__ void rot_ry(float* sr, float* si, float c, float s) {
    #pragma unroll
    for (int k = 0; k < 16; k++) {
        if (k & STR) continue;
        int k1 = k | STR;
        float ar0 = sr[k], ai0 = si[k], ar1 = sr[k1], ai1 = si[k1];
        // U = [[c, -s],[s, c]]
        sr[k]  = c * ar0 - s * ar1;
        si[k]  = c * ai0 - s * ai1;
        sr[k1] = s * ar0 + c * ar1;
        si[k1] = s * ai0 + c * ai1;
    }
}

template <int STR>
__device__ __forceinline__ void rot_rz(float* sr, float* si, float c, float s) {
    #pragma unroll
    for (int k = 0; k < 16; k++) {
        float ar = sr[k], ai = si[k];
        if (k & STR) { // * (c + i s)
            sr[k] = c * ar - s * ai;
            si[k] = c * ai + s * ar;
        } else {       // * (c - i s)
            sr[k] = c * ar + s * ai;
            si[k] = c * ai - s * ar;
        }
    }
}

__device__ __forceinline__ void cnot_c3_t0(float* sr, float* si) {
    // control = wire3 = bit0, target = wire0 = bit3: swap (k, k^8) where k&1
    #pragma unroll
    for (int k = 1; k < 8; k += 2) {
        int k1 = k | 8;
        float tr = sr[k], ti = si[k];
        sr[k] = sr[k1]; si[k] = si[k1];
        sr[k1] = tr;    si[k1] = ti;
    }
}

__global__ void k_quantum(const float* __restrict__ rl_params,
                          float* __restrict__ out) {
    __shared__ float gc[23], gs[23];
    int tid = threadIdx.x;
    if (tid < 23) {
        float t = rl_params[tid] * 0.5f;
        gc[tid] = cosf(t);
        gs[tid] = sinf(t);
    }
    __syncthreads();

    int b = blockIdx.x * blockDim.x + tid;
    if (b >= BATCH) return;

    float sr[16], si[16];
    #pragma unroll
    for (int k = 0; k < 16; k++) { sr[k] = 0.0f; si[k] = 0.0f; }
    sr[0] = 1.0f;

    // Encoder: RX(feat[w]) on each wire (bn applied on the fly)
    {
        float f, s, c;
        f = (g_feat[b * 4 + 0] * g_scsh[0] + g_scsh[4]) * 0.5f;
        __sincosf(f, &s, &c);  // fine; replaced by precise below if needed
        s = sinf(f); c = cosf(f);
        rot_rx<8>(sr, si, c, s);
        f = (g_feat[b * 4 + 1] * g_scsh[1] + g_scsh[5]) * 0.5f;
        s = sinf(f); c = cosf(f);
        rot_rx<4>(sr, si, c, s);
        f = (g_feat[b * 4 + 2] * g_scsh[2] + g_scsh[6]) * 0.5f;
        s = sinf(f); c = cosf(f);
        rot_rx<2>(sr, si, c, s);
        f = (g_feat[b * 4 + 3] * g_scsh[3] + g_scsh[7]) * 0.5f;
        s = sinf(f); c = cosf(f);
        rot_rx<1>(sr, si, c, s);
    }

    // Random layer: 7x [RX w0, RY w1, RZ w2, CNOT(3,0)] then RX w0, RY w1
    #pragma unroll
    for (int r = 0; r < 7; r++) {
        rot_rx<8>(sr, si, gc[3 * r],     gs[3 * r]);
        rot_ry<4>(sr, si, gc[3 * r + 1], gs[3 * r + 1]);
        rot_rz<2>(sr, si, gc[3 * r + 2], gs[3 * r + 2]);
        cnot_c3_t0(sr, si);
    }
    rot_rx<8>(sr, si, gc[21], gs[21]);
    rot_ry<4>(sr, si, gc[22], gs[22]);

    // probs @ ZTAB
    float p[16];
    #pragma unroll
    for (int k = 0; k < 16; k++) p[k] = sr[k] * sr[k] + si[k] * si[k];
    #pragma unroll
    for (int w = 0; w < 4; w++) {
        int str = 8 >> w;
        float acc = 0.0f;
        #pragma unroll
        for (int k = 0; k < 16; k++) acc += (k & str) ? -p[k] : p[k];
        out[b * 4 + w] = acc;
    }
}

// ---------------------------------------------------------------------------
// Launch
// ---------------------------------------------------------------------------
extern "C" void kernel_launch(void* const* d_in, const int* in_sizes, int n_in,
                              void* d_out, int out_size) {
    const float* x       = (const float*)d_in[0];
    const float* conv1_w = (const float*)d_in[1];
    const float* conv1_b = (const float*)d_in[2];
    const float* conv2_w = (const float*)d_in[3];
    const float* conv2_b = (const float*)d_in[4];
    const float* fc1_w   = (const float*)d_in[5];
    const float* fc1_b   = (const float*)d_in[6];
    const float* fc2_w   = (const float*)d_in[7];
    const float* fc2_b   = (const float*)d_in[8];
    const float* bn_g    = (const float*)d_in[9];
    const float* bn_b    = (const float*)d_in[10];
    const float* rl      = (const float*)d_in[11];
    float* out = (float*)d_out;

    int B = in_sizes[0] / 784;  // 8192

    k_transpose_fc1<<<(64 * 784 + 255) / 256, 256>>>(fc1_w);
    k_conv1<<<B, 256>>>(x, conv1_w, conv1_b);
    k_conv2<<<B, 256>>>(conv2_w, conv2_b);
    k_fc<<<B / 8, 256>>>(fc1_b, fc2_w, fc2_b);
    k_stats<<<1, 256>>>(bn_g, bn_b);
    k_quantum<<<(B + 255) / 256, 256>>>(rl, out);
}

// round 2
// speedup vs baseline: 1.7638x; 1.7638x over previous
#include <cuda_runtime.h>
#include <math.h>

#define BATCH 8192

// ---------------------------------------------------------------------------
// Scratch
// ---------------------------------------------------------------------------
__device__ float g_flat[BATCH * 784]; // conv2 output [B,784]
__device__ float g_feat[BATCH * 4];   // fc2 output   [B,4]
__device__ float g_scsh[8];           // [scale0..3, shift0..3]

// ---------------------------------------------------------------------------
// K1: fused conv1+pool, conv2+pool. 2 samples per block, 224 threads.
// All intermediate data stays in (zero-padded) SMEM -> branchless conv,
// register-blocked inner loops (LDS/FMA ~ 0.06).
// ---------------------------------------------------------------------------
__global__ __launch_bounds__(224, 2)
void k_conv(const float* __restrict__ x,
            const float* __restrict__ w1, const float* __restrict__ b1,
            const float* __restrict__ w2, const float* __restrict__ b2) {
    __shared__ float sx[2][30][30];     // padded input  (1800 f)
    __shared__ float sp[2][8][16][16];  // padded conv1 pooled out (4096 f)
    __shared__ float sw1[72], sw2[1152];
    __shared__ float sb1[8], sb2[16];

    const int tid = threadIdx.x;
    const int b0 = blockIdx.x * 2;

    // Zero padded buffers + stage weights
    for (int i = tid; i < 1800; i += 224) ((float*)sx)[i] = 0.0f;
    for (int i = tid; i < 4096; i += 224) ((float*)sp)[i] = 0.0f;
    for (int i = tid; i < 1152; i += 224) sw2[i] = w2[i];
    if (tid < 72) sw1[tid] = w1[tid];
    if (tid < 8)  sb1[tid] = b1[tid];
    if (tid < 16) sb2[tid] = b2[tid];
    __syncthreads();

    // Fill interior of padded input
    for (int i = tid; i < 2 * 784; i += 224) {
        int s = i / 784, r = i % 784;
        int yy = r / 28, xx = r % 28;
        sx[s][yy + 1][xx + 1] = x[(b0 + s) * 784 + r];
    }
    __syncthreads();

    // -------- conv1 (1->8) + relu + pool -> sp (padded) --------
    {
        const int s = tid / 112, r = tid % 112;
        const int oc = r / 14, y2 = r % 14;
        float wr[9];
        #pragma unroll
        for (int i = 0; i < 9; i++) wr[i] = sw1[oc * 9 + i];
        const float bias = sb1[oc];

        #pragma unroll
        for (int xh = 0; xh < 2; xh++) {
            float in[4][16];
            #pragma unroll
            for (int rr = 0; rr < 3; rr++)
                #pragma unroll
                for (int c = 0; c < 16; c++)
                    in[rr][c] = sx[s][2 * y2 + rr][xh * 14 + c];

            float m[7];
            // conv row 2*y2 : padded rows in[0..2]
            #pragma unroll
            for (int xx = 0; xx < 14; xx++) {
                float a = bias;
                #pragma unroll
                for (int dy = 0; dy < 3; dy++)
                    #pragma unroll
                    for (int dx = 0; dx < 3; dx++)
                        a = fmaf(in[dy][xx + dx], wr[dy * 3 + dx], a);
                a = fmaxf(a, 0.0f);
                if ((xx & 1) == 0) m[xx >> 1] = a;
                else               m[xx >> 1] = fmaxf(m[xx >> 1], a);
            }
            #pragma unroll
            for (int c = 0; c < 16; c++)
                in[3][c] = sx[s][2 * y2 + 3][xh * 14 + c];
            // conv row 2*y2+1 : padded rows in[1..3]
            #pragma unroll
            for (int xx = 0; xx < 14; xx++) {
                float a = bias;
                #pragma unroll
                for (int dy = 0; dy < 3; dy++)
                    #pragma unroll
                    for (int dx = 0; dx < 3; dx++)
                        a = fmaf(in[dy + 1][xx + dx], wr[dy * 3 + dx], a);
                a = fmaxf(a, 0.0f);
                m[xx >> 1] = fmaxf(m[xx >> 1], a);
            }
            #pragma unroll
            for (int p = 0; p < 7; p++)
                sp[s][oc][y2 + 1][xh * 7 + p + 1] = m[p];
        }
    }
    __syncthreads();

    // -------- conv2 (8->16) + relu + pool -> g_flat --------
    {
        const int s = tid / 112, r = tid % 112;
        const int oc = r / 7, y2 = r % 7;
        float acc0[14], acc1[14];
        #pragma unroll
        for (int i = 0; i < 14; i++) { acc0[i] = 0.0f; acc1[i] = 0.0f; }

        #pragma unroll
        for (int ic = 0; ic < 8; ic++) {
            float wr[9];
            #pragma unroll
            for (int i = 0; i < 9; i++) wr[i] = sw2[oc * 72 + ic * 9 + i];

            const float* rowp = &sp[s][ic][2 * y2][0];
            float i0[16], i1[16], i2[16];
            #pragma unroll
            for (int q = 0; q < 4; q++) {
                ((float4*)i0)[q] = ((const float4*)(rowp))[q];
                ((float4*)i1)[q] = ((const float4*)(rowp + 16))[q];
                ((float4*)i2)[q] = ((const float4*)(rowp + 32))[q];
            }
            // conv row 2*y2 uses padded rows i0,i1,i2
            #pragma unroll
            for (int xx = 0; xx < 14; xx++) {
                float a = acc0[xx];
                a = fmaf(i0[xx], wr[0], a); a = fmaf(i0[xx+1], wr[1], a); a = fmaf(i0[xx+2], wr[2], a);
                a = fmaf(i1[xx], wr[3], a); a = fmaf(i1[xx+1], wr[4], a); a = fmaf(i1[xx+2], wr[5], a);
                a = fmaf(i2[xx], wr[6], a); a = fmaf(i2[xx+1], wr[7], a); a = fmaf(i2[xx+2], wr[8], a);
                acc0[xx] = a;
            }
            // load row 2*y2+3 into i0 (dead) ; conv row 2*y2+1 uses i1,i2,i0
            #pragma unroll
            for (int q = 0; q < 4; q++)
                ((float4*)i0)[q] = ((const float4*)(rowp + 48))[q];
            #pragma unroll
            for (int xx = 0; xx < 14; xx++) {
                float a = acc1[xx];
                a = fmaf(i1[xx], wr[0], a); a = fmaf(i1[xx+1], wr[1], a); a = fmaf(i1[xx+2], wr[2], a);
                a = fmaf(i2[xx], wr[3], a); a = fmaf(i2[xx+1], wr[4], a); a = fmaf(i2[xx+2], wr[5], a);
                a = fmaf(i0[xx], wr[6], a); a = fmaf(i0[xx+1], wr[7], a); a = fmaf(i0[xx+2], wr[8], a);
                acc1[xx] = a;
            }
        }

        const float bias = sb2[oc];
        float* dst = &g_flat[(b0 + s) * 784 + oc * 49 + y2 * 7];
        #pragma unroll
        for (int p = 0; p < 7; p++) {
            float a = fmaxf(acc0[2 * p] + bias, 0.0f);
            a = fmaxf(a, fmaxf(acc0[2 * p + 1] + bias, 0.0f));
            a = fmaxf(a, fmaxf(acc1[2 * p] + bias, 0.0f));
            a = fmaxf(a, fmaxf(acc1[2 * p + 1] + bias, 0.0f));
            dst[p] = a;
        }
    }
}

// ---------------------------------------------------------------------------
// K2: FC1(784->64)+relu + FC2(64->4), tiled GEMM. 64 samples/block.
// Thread tile: 2 outputs x 8 samples. K-tile = 56, float4 loads.
// ---------------------------------------------------------------------------
#define FC_STRIDE 60
__global__ __launch_bounds__(256)
void k_fc(const float* __restrict__ fc1_w, const float* __restrict__ fc1_b,
          const float* __restrict__ fc2_w, const float* __restrict__ fc2_b) {
    __shared__ float sAW[2 * 64 * FC_STRIDE]; // sA | sW ; reused as sh after loop
    __shared__ float sw2[256];
    float* sA = sAW;
    float* sW = sAW + 64 * FC_STRIDE;

    const int tid = threadIdx.x;
    const int s0 = blockIdx.x * 64;
    const int jj = tid & 31;     // output pair {jj, jj+32}
    const int ss = tid >> 5;     // sample group: samples ss*8 .. ss*8+7

    for (int i = tid; i < 256; i += 256) sw2[i] = fc2_w[i];

    float acc[2][8];
    #pragma unroll
    for (int u = 0; u < 8; u++) { acc[0][u] = 0.0f; acc[1][u] = 0.0f; }

    for (int kt = 0; kt < 784; kt += 56) {
        __syncthreads();
        #pragma unroll
        for (int i = tid; i < 64 * 56; i += 256) {
            int r = i / 56, kk = i % 56;
            sA[r * FC_STRIDE + kk] = g_flat[(s0 + r) * 784 + kt + kk];
            sW[r * FC_STRIDE + kk] = fc1_w[r * 784 + kt + kk];
        }
        __syncthreads();
        #pragma unroll
        for (int k4 = 0; k4 < 14; k4++) {
            float4 w0 = *(const float4*)&sW[jj * FC_STRIDE + k4 * 4];
            float4 w1 = *(const float4*)&sW[(jj + 32) * FC_STRIDE + k4 * 4];
            #pragma unroll
            for (int u = 0; u < 8; u++) {
                float4 a = *(const float4*)&sA[(ss * 8 + u) * FC_STRIDE + k4 * 4];
                float t0 = acc[0][u], t1 = acc[1][u];
                t0 = fmaf(a.x, w0.x, t0); t1 = fmaf(a.x, w1.x, t1);
                t0 = fmaf(a.y, w0.y, t0); t1 = fmaf(a.y, w1.y, t1);
                t0 = fmaf(a.z, w0.z, t0); t1 = fmaf(a.z, w1.z, t1);
                t0 = fmaf(a.w, w0.w, t0); t1 = fmaf(a.w, w1.w, t1);
                acc[0][u] = t0; acc[1][u] = t1;
            }
        }
    }

    // relu + bias, stash h into reused SMEM (sh stride 65)
    __syncthreads();
    float* sh = sAW;
    const float bj0 = fc1_b[jj], bj1 = fc1_b[jj + 32];
    #pragma unroll
    for (int u = 0; u < 8; u++) {
        sh[(ss * 8 + u) * 65 + jj]      = fmaxf(acc[0][u] + bj0, 0.0f);
        sh[(ss * 8 + u) * 65 + jj + 32] = fmaxf(acc[1][u] + bj1, 0.0f);
    }
    __syncthreads();

    // FC2: 64 samples x 4 channels = 256 threads
    {
        const int s = tid >> 2, c = tid & 3;
        float a = fc2_b[c];
        const float* hp = &sh[s * 65];
        const float* wc = &sw2[c * 64];
        #pragma unroll
        for (int j = 0; j < 64; j++) a = fmaf(hp[j], wc[j], a);
        g_feat[(s0 + s) * 4 + c] = a;
    }
}

// ---------------------------------------------------------------------------
// K3: batch mean/var -> scale/shift (double accumulation for safety)
// ---------------------------------------------------------------------------
__global__ void k_stats(const float* __restrict__ bn_g,
                        const float* __restrict__ bn_b) {
    __shared__ double ss[256][8];
    const int tid = threadIdx.x;
    double sum[4] = {0, 0, 0, 0}, sq[4] = {0, 0, 0, 0};
    for (int s = tid; s < BATCH; s += 256) {
        float4 f = ((const float4*)g_feat)[s];
        double v;
        v = (double)f.x; sum[0] += v; sq[0] += v * v;
        v = (double)f.y; sum[1] += v; sq[1] += v * v;
        v = (double)f.z; sum[2] += v; sq[2] += v * v;
        v = (double)f.w; sum[3] += v; sq[3] += v * v;
    }
    #pragma unroll
    for (int c = 0; c < 4; c++) { ss[tid][c] = sum[c]; ss[tid][4 + c] = sq[c]; }
    __syncthreads();
    for (int off = 128; off >= 1; off >>= 1) {
        if (tid < off) {
            #pragma unroll
            for (int k = 0; k < 8; k++) ss[tid][k] += ss[tid + off][k];
        }
        __syncthreads();
    }
    if (tid < 4) {
        double m = ss[0][tid] / (double)BATCH;
        double var = ss[0][4 + tid] / (double)BATCH - m * m;
        float scale = (float)((double)bn_g[tid] / sqrt(var + 1e-5));
        float shift = bn_b[tid] - (float)m * scale;
        g_scsh[tid] = scale;
        g_scsh[4 + tid] = shift;
    }
}

// ---------------------------------------------------------------------------
// K4: quantum state-vector sim + PauliZ measurement (verified correct in R1)
// ---------------------------------------------------------------------------
template <int STR>
__device__ __forceinline__ void rot_rx(float* sr, float* si, float c, float s) {
    #pragma unroll
    for (int k = 0; k < 16; k++) {
        if (k & STR) continue;
        int k1 = k | STR;
        float ar0 = sr[k], ai0 = si[k], ar1 = sr[k1], ai1 = si[k1];
        sr[k]  = c * ar0 + s * ai1;
        si[k]  = c * ai0 - s * ar1;
        sr[k1] = s * ai0 + c * ar1;
        si[k1] = -s * ar0 + c * ai1;
    }
}

template <int STR>
__device__ __forceinline__ void rot_ry(float* sr, float* si, float c, float s) {
    #pragma unroll
    for (int k = 0; k < 16; k++) {
        if (k & STR) continue;
        int k1 = k | STR;
        float ar0 = sr[k], ai0 = si[k], ar1 = sr[k1], ai1 = si[k1];
        sr[k]  = c * ar0 - s * ar1;
        si[k]  = c * ai0 - s * ai1;
        sr[k1] = s * ar0 + c * ar1;
        si[k1] = s * ai0 + c * ai1;
    }
}

template <int STR>
__device__ __forceinline__ void rot_rz(float* sr, float* si, float c, float s) {
    #pragma unroll
    for (int k = 0; k < 16; k++) {
        float ar = sr[k], ai = si[k];
        if (k & STR) { sr[k] = c * ar - s * ai; si[k] = c * ai + s * ar; }
        else         { sr[k] = c * ar + s * ai; si[k] = c * ai - s * ar; }
    }
}

__device__ __forceinline__ void cnot_c3_t0(float* sr, float* si) {
    #pragma unroll
    for (int k = 1; k < 8; k += 2) {
        int k1 = k | 8;
        float tr = sr[k], ti = si[k];
        sr[k] = sr[k1]; si[k] = si[k1];
        sr[k1] = tr;    si[k1] = ti;
    }
}

__global__ void k_quantum(const float* __restrict__ rl_params,
                          float* __restrict__ out) {
    __shared__ float gc[23], gs[23];
    const int tid = threadIdx.x;
    if (tid < 23) {
        float t = rl_params[tid] * 0.5f;
        gc[tid] = cosf(t);
        gs[tid] = sinf(t);
    }
    __syncthreads();

    const int b = blockIdx.x * blockDim.x + tid;
    if (b >= BATCH) return;

    float sr[16], si[16];
    #pragma unroll
    for (int k = 0; k < 16; k++) { sr[k] = 0.0f; si[k] = 0.0f; }
    sr[0] = 1.0f;

    float4 f4 = ((const float4*)g_feat)[b];
    {
        float f, s, c;
        f = (f4.x * g_scsh[0] + g_scsh[4]) * 0.5f; s = sinf(f); c = cosf(f);
        rot_rx<8>(sr, si, c, s);
        f = (f4.y * g_scsh[1] + g_scsh[5]) * 0.5f; s = sinf(f); c = cosf(f);
        rot_rx<4>(sr, si, c, s);
        f = (f4.z * g_scsh[2] + g_scsh[6]) * 0.5f; s = sinf(f); c = cosf(f);
        rot_rx<2>(sr, si, c, s);
        f = (f4.w * g_scsh[3] + g_scsh[7]) * 0.5f; s = sinf(f); c = cosf(f);
        rot_rx<1>(sr, si, c, s);
    }

    #pragma unroll
    for (int r = 0; r < 7; r++) {
        rot_rx<8>(sr, si, gc[3 * r],     gs[3 * r]);
        rot_ry<4>(sr, si, gc[3 * r + 1], gs[3 * r + 1]);
        rot_rz<2>(sr, si, gc[3 * r + 2], gs[3 * r + 2]);
        cnot_c3_t0(sr, si);
    }
    rot_rx<8>(sr, si, gc[21], gs[21]);
    rot_ry<4>(sr, si, gc[22], gs[22]);

    float p[16];
    #pragma unroll
    for (int k = 0; k < 16; k++) p[k] = sr[k] * sr[k] + si[k] * si[k];
    #pragma unroll
    for (int w = 0; w < 4; w++) {
        int str = 8 >> w;
        float acc = 0.0f;
        #pragma unroll
        for (int k = 0; k < 16; k++) acc += (k & str) ? -p[k] : p[k];
        out[b * 4 + w] = acc;
    }
}

// ---------------------------------------------------------------------------
// Launch
// ---------------------------------------------------------------------------
extern "C" void kernel_launch(void* const* d_in, const int* in_sizes, int n_in,
                              void* d_out, int out_size) {
    const float* x       = (const float*)d_in[0];
    const float* conv1_w = (const float*)d_in[1];
    const float* conv1_b = (const float*)d_in[2];
    const float* conv2_w = (const float*)d_in[3];
    const float* conv2_b = (const float*)d_in[4];
    const float* fc1_w   = (const float*)d_in[5];
    const float* fc1_b   = (const float*)d_in[6];
    const float* fc2_w   = (const float*)d_in[7];
    const float* fc2_b   = (const float*)d_in[8];
    const float* bn_g    = (const float*)d_in[9];
    const float* bn_b    = (const float*)d_in[10];
    const float* rl      = (const float*)d_in[11];
    float* out = (float*)d_out;

    k_conv<<<BATCH / 2, 224>>>(x, conv1_w, conv1_b, conv2_w, conv2_b);
    k_fc<<<BATCH / 64, 256>>>(fc1_w, fc1_b, fc2_w, fc2_b);
    k_stats<<<1, 256>>>(bn_g, bn_b);
    k_quantum<<<BATCH / 256, 256>>>(rl, out);
}

// round 3
// speedup vs baseline: 3.9990x; 2.2673x over previous
#include <cuda_runtime.h>
#include <math.h>

#define BATCH 8192

// sp layout constants (bank-conflict-free-ish padded layout)
#define RS 20            // row stride in floats (16B-aligned for float4)
#define PS 324           // plane (channel) stride: 16*20+4 -> bank step 4 per oc
#define SS (8 * PS)      // sample stride: 2592 floats

// ---------------------------------------------------------------------------
// Scratch
// ---------------------------------------------------------------------------
__device__ float g_flat[BATCH * 784]; // conv2 output [B,784]
__device__ float g_feat[BATCH * 4];   // fc2 output   [B,4]
__device__ float g_scsh[8];           // [scale0..3, shift0..3]

// ---------------------------------------------------------------------------
// K1: fused conv1+pool, conv2+pool. 2 samples/block, 224 threads.
// oc-fastest thread maps -> smem loads are warp-broadcast; padded strides
// kill bank conflicts.
// ---------------------------------------------------------------------------
__global__ __launch_bounds__(224, 2)
void k_conv(const float* __restrict__ x,
            const float* __restrict__ w1, const float* __restrict__ b1,
            const float* __restrict__ w2, const float* __restrict__ b2) {
    __shared__ float sx[2][30][30];     // padded input (1800 f)
    __shared__ float sp[2 * SS];        // padded conv1 pooled out (5184 f)
    __shared__ float sw1[72];
    __shared__ float sw2p[16 * 73];     // padded conv2 weights
    __shared__ float sb1[8], sb2[16];

    const int tid = threadIdx.x;
    const int b0 = blockIdx.x * 2;

    for (int i = tid; i < 1800; i += 224) ((float*)sx)[i] = 0.0f;
    for (int i = tid; i < 2 * SS; i += 224) sp[i] = 0.0f;
    for (int i = tid; i < 1152; i += 224) {
        int oc = i / 72, rem = i % 72;
        sw2p[oc * 73 + rem] = w2[i];
    }
    if (tid < 72) sw1[tid] = w1[tid];
    if (tid < 8)  sb1[tid] = b1[tid];
    if (tid < 16) sb2[tid] = b2[tid];
    __syncthreads();

    for (int i = tid; i < 2 * 784; i += 224) {
        int s = i / 784, r = i % 784;
        int yy = r / 28, xx = r % 28;
        sx[s][yy + 1][xx + 1] = x[(b0 + s) * 784 + r];
    }
    __syncthreads();

    // -------- conv1 (1->8) + relu + pool -> sp --------
    {
        const int oc = tid & 7;
        const int rest = tid >> 3;      // 0..27
        const int y2 = rest % 14;
        const int s = rest / 14;
        float wr[9];
        #pragma unroll
        for (int i = 0; i < 9; i++) wr[i] = sw1[oc * 9 + i];
        const float bias = sb1[oc];
        float* spb = &sp[s * SS + oc * PS + (y2 + 1) * RS];

        #pragma unroll
        for (int xh = 0; xh < 2; xh++) {
            float in[4][16];
            #pragma unroll
            for (int rr = 0; rr < 3; rr++)
                #pragma unroll
                for (int c = 0; c < 16; c++)
                    in[rr][c] = sx[s][2 * y2 + rr][xh * 14 + c];

            float m[7];
            #pragma unroll
            for (int xx = 0; xx < 14; xx++) {
                float a = bias;
                #pragma unroll
                for (int dy = 0; dy < 3; dy++)
                    #pragma unroll
                    for (int dx = 0; dx < 3; dx++)
                        a = fmaf(in[dy][xx + dx], wr[dy * 3 + dx], a);
                a = fmaxf(a, 0.0f);
                if ((xx & 1) == 0) m[xx >> 1] = a;
                else               m[xx >> 1] = fmaxf(m[xx >> 1], a);
            }
            #pragma unroll
            for (int c = 0; c < 16; c++)
                in[3][c] = sx[s][2 * y2 + 3][xh * 14 + c];
            #pragma unroll
            for (int xx = 0; xx < 14; xx++) {
                float a = bias;
                #pragma unroll
                for (int dy = 0; dy < 3; dy++)
                    #pragma unroll
                    for (int dx = 0; dx < 3; dx++)
                        a = fmaf(in[dy + 1][xx + dx], wr[dy * 3 + dx], a);
                a = fmaxf(a, 0.0f);
                m[xx >> 1] = fmaxf(m[xx >> 1], a);
            }
            #pragma unroll
            for (int p = 0; p < 7; p++)
                spb[xh * 7 + p + 1] = m[p];
        }
    }
    __syncthreads();

    // -------- conv2 (8->16) + relu + pool -> g_flat --------
    {
        const int oc = tid & 15;
        const int rest = tid >> 4;     // 0..13
        const int y2 = rest % 7;
        const int s = rest / 7;
        float acc0[14], acc1[14];
        #pragma unroll
        for (int i = 0; i < 14; i++) { acc0[i] = 0.0f; acc1[i] = 0.0f; }

        #pragma unroll
        for (int ic = 0; ic < 8; ic++) {
            float wr[9];
            #pragma unroll
            for (int i = 0; i < 9; i++) wr[i] = sw2p[oc * 73 + ic * 9 + i];

            const float* rowp = &sp[s * SS + ic * PS + (2 * y2) * RS];
            float i0[16], i1[16], i2[16];
            #pragma unroll
            for (int q = 0; q < 4; q++) {
                ((float4*)i0)[q] = ((const float4*)(rowp))[q];
                ((float4*)i1)[q] = ((const float4*)(rowp + RS))[q];
                ((float4*)i2)[q] = ((const float4*)(rowp + 2 * RS))[q];
            }
            #pragma unroll
            for (int xx = 0; xx < 14; xx++) {
                float a = acc0[xx];
                a = fmaf(i0[xx], wr[0], a); a = fmaf(i0[xx+1], wr[1], a); a = fmaf(i0[xx+2], wr[2], a);
                a = fmaf(i1[xx], wr[3], a); a = fmaf(i1[xx+1], wr[4], a); a = fmaf(i1[xx+2], wr[5], a);
                a = fmaf(i2[xx], wr[6], a); a = fmaf(i2[xx+1], wr[7], a); a = fmaf(i2[xx+2], wr[8], a);
                acc0[xx] = a;
            }
            #pragma unroll
            for (int q = 0; q < 4; q++)
                ((float4*)i0)[q] = ((const float4*)(rowp + 3 * RS))[q];
            #pragma unroll
            for (int xx = 0; xx < 14; xx++) {
                float a = acc1[xx];
                a = fmaf(i1[xx], wr[0], a); a = fmaf(i1[xx+1], wr[1], a); a = fmaf(i1[xx+2], wr[2], a);
                a = fmaf(i2[xx], wr[3], a); a = fmaf(i2[xx+1], wr[4], a); a = fmaf(i2[xx+2], wr[5], a);
                a = fmaf(i0[xx], wr[6], a); a = fmaf(i0[xx+1], wr[7], a); a = fmaf(i0[xx+2], wr[8], a);
                acc1[xx] = a;
            }
        }

        const float bias = sb2[oc];
        float* dst = &g_flat[(b0 + s) * 784 + oc * 49 + y2 * 7];
        #pragma unroll
        for (int p = 0; p < 7; p++) {
            float a = fmaxf(acc0[2 * p] + bias, 0.0f);
            a = fmaxf(a, fmaxf(acc0[2 * p + 1] + bias, 0.0f));
            a = fmaxf(a, fmaxf(acc1[2 * p] + bias, 0.0f));
            a = fmaxf(a, fmaxf(acc1[2 * p + 1] + bias, 0.0f));
            dst[p] = a;
        }
    }
}

// ---------------------------------------------------------------------------
// K2: FC1(784->64)+relu + FC2(64->4), tiled GEMM. 64 samples/block.
// ---------------------------------------------------------------------------
#define FC_STRIDE 60
__global__ __launch_bounds__(256)
void k_fc(const float* __restrict__ fc1_w, const float* __restrict__ fc1_b,
          const float* __restrict__ fc2_w, const float* __restrict__ fc2_b) {
    __shared__ float sAW[2 * 64 * FC_STRIDE];
    __shared__ float sw2[256];
    float* sA = sAW;
    float* sW = sAW + 64 * FC_STRIDE;

    const int tid = threadIdx.x;
    const int s0 = blockIdx.x * 64;
    const int jj = tid & 31;
    const int ss = tid >> 5;

    for (int i = tid; i < 256; i += 256) sw2[i] = fc2_w[i];

    float acc[2][8];
    #pragma unroll
    for (int u = 0; u < 8; u++) { acc[0][u] = 0.0f; acc[1][u] = 0.0f; }

    for (int kt = 0; kt < 784; kt += 56) {
        __syncthreads();
        #pragma unroll
        for (int i = tid; i < 64 * 56; i += 256) {
            int r = i / 56, kk = i % 56;
            sA[r * FC_STRIDE + kk] = g_flat[(s0 + r) * 784 + kt + kk];
            sW[r * FC_STRIDE + kk] = fc1_w[r * 784 + kt + kk];
        }
        __syncthreads();
        #pragma unroll
        for (int k4 = 0; k4 < 14; k4++) {
            float4 w0 = *(const float4*)&sW[jj * FC_STRIDE + k4 * 4];
            float4 w1 = *(const float4*)&sW[(jj + 32) * FC_STRIDE + k4 * 4];
            #pragma unroll
            for (int u = 0; u < 8; u++) {
                float4 a = *(const float4*)&sA[(ss * 8 + u) * FC_STRIDE + k4 * 4];
                float t0 = acc[0][u], t1 = acc[1][u];
                t0 = fmaf(a.x, w0.x, t0); t1 = fmaf(a.x, w1.x, t1);
                t0 = fmaf(a.y, w0.y, t0); t1 = fmaf(a.y, w1.y, t1);
                t0 = fmaf(a.z, w0.z, t0); t1 = fmaf(a.z, w1.z, t1);
                t0 = fmaf(a.w, w0.w, t0); t1 = fmaf(a.w, w1.w, t1);
                acc[0][u] = t0; acc[1][u] = t1;
            }
        }
    }

    __syncthreads();
    float* sh = sAW;
    const float bj0 = fc1_b[jj], bj1 = fc1_b[jj + 32];
    #pragma unroll
    for (int u = 0; u < 8; u++) {
        sh[(ss * 8 + u) * 65 + jj]      = fmaxf(acc[0][u] + bj0, 0.0f);
        sh[(ss * 8 + u) * 65 + jj + 32] = fmaxf(acc[1][u] + bj1, 0.0f);
    }
    __syncthreads();

    {
        const int s = tid >> 2, c = tid & 3;
        float a = fc2_b[c];
        const float* hp = &sh[s * 65];
        const float* wc = &sw2[c * 64];
        #pragma unroll
        for (int j = 0; j < 64; j++) a = fmaf(hp[j], wc[j], a);
        g_feat[(s0 + s) * 4 + c] = a;
    }
}

// ---------------------------------------------------------------------------
// K3: batch mean/var -> scale/shift
// ---------------------------------------------------------------------------
__global__ void k_stats(const float* __restrict__ bn_g,
                        const float* __restrict__ bn_b) {
    __shared__ double ss[256][8];
    const int tid = threadIdx.x;
    double sum[4] = {0, 0, 0, 0}, sq[4] = {0, 0, 0, 0};
    for (int s = tid; s < BATCH; s += 256) {
        float4 f = ((const float4*)g_feat)[s];
        double v;
        v = (double)f.x; sum[0] += v; sq[0] += v * v;
        v = (double)f.y; sum[1] += v; sq[1] += v * v;
        v = (double)f.z; sum[2] += v; sq[2] += v * v;
        v = (double)f.w; sum[3] += v; sq[3] += v * v;
    }
    #pragma unroll
    for (int c = 0; c < 4; c++) { ss[tid][c] = sum[c]; ss[tid][4 + c] = sq[c]; }
    __syncthreads();
    for (int off = 128; off >= 1; off >>= 1) {
        if (tid < off) {
            #pragma unroll
            for (int k = 0; k < 8; k++) ss[tid][k] += ss[tid + off][k];
        }
        __syncthreads();
    }
    if (tid < 4) {
        double m = ss[0][tid] / (double)BATCH;
        double var = ss[0][4 + tid] / (double)BATCH - m * m;
        float scale = (float)((double)bn_g[tid] / sqrt(var + 1e-5));
        float shift = bn_b[tid] - (float)m * scale;
        g_scsh[tid] = scale;
        g_scsh[4 + tid] = shift;
    }
}

// ---------------------------------------------------------------------------
// K4: quantum state-vector sim + PauliZ measurement
// ---------------------------------------------------------------------------
template <int STR>
__device__ __forceinline__ void rot_rx(float* sr, float* si, float c, float s) {
    #pragma unroll
    for (int k = 0; k < 16; k++) {
        if (k & STR) continue;
        int k1 = k | STR;
        float ar0 = sr[k], ai0 = si[k], ar1 = sr[k1], ai1 = si[k1];
        sr[k]  = c * ar0 + s * ai1;
        si[k]  = c * ai0 - s * ar1;
        sr[k1] = s * ai0 + c * ar1;
        si[k1] = -s * ar0 + c * ai1;
    }
}

template <int STR>
__device__ __forceinline__ void rot_ry(float* sr, float* si, float c, float s) {
    #pragma unroll
    for (int k = 0; k < 16; k++) {
        if (k & STR) continue;
        int k1 = k | STR;
        float ar0 = sr[k], ai0 = si[k], ar1 = sr[k1], ai1 = si[k1];
        sr[k]  = c * ar0 - s * ar1;
        si[k]  = c * ai0 - s * ai1;
        sr[k1] = s * ar0 + c * ar1;
        si[k1] = s * ai0 + c * ai1;
    }
}

template <int STR>
__device__ __forceinline__ void rot_rz(float* sr, float* si, float c, float s) {
    #pragma unroll
    for (int k = 0; k < 16; k++) {
        float ar = sr[k], ai = si[k];
        if (k & STR) { sr[k] = c * ar - s * ai; si[k] = c * ai + s * ar; }
        else         { sr[k] = c * ar + s * ai; si[k] = c * ai - s * ar; }
    }
}

__device__ __forceinline__ void cnot_c3_t0(float* sr, float* si) {
    #pragma unroll
    for (int k = 1; k < 8; k += 2) {
        int k1 = k | 8;
        float tr = sr[k], ti = si[k];
        sr[k] = sr[k1]; si[k] = si[k1];
        sr[k1] = tr;    si[k1] = ti;
    }
}

__global__ void k_quantum(const float* __restrict__ rl_params,
                          float* __restrict__ out) {
    __shared__ float gc[23], gs[23];
    const int tid = threadIdx.x;
    if (tid < 23) {
        float t = rl_params[tid] * 0.5f;
        gc[tid] = cosf(t);
        gs[tid] = sinf(t);
    }
    __syncthreads();

    const int b = blockIdx.x * blockDim.x + tid;
    if (b >= BATCH) return;

    float sr[16], si[16];
    #pragma unroll
    for (int k = 0; k < 16; k++) { sr[k] = 0.0f; si[k] = 0.0f; }
    sr[0] = 1.0f;

    float4 f4 = ((const float4*)g_feat)[b];
    {
        float f, s, c;
        f = (f4.x * g_scsh[0] + g_scsh[4]) * 0.5f; s = sinf(f); c = cosf(f);
        rot_rx<8>(sr, si, c, s);
        f = (f4.y * g_scsh[1] + g_scsh[5]) * 0.5f; s = sinf(f); c = cosf(f);
        rot_rx<4>(sr, si, c, s);
        f = (f4.z * g_scsh[2] + g_scsh[6]) * 0.5f; s = sinf(f); c = cosf(f);
        rot_rx<2>(sr, si, c, s);
        f = (f4.w * g_scsh[3] + g_scsh[7]) * 0.5f; s = sinf(f); c = cosf(f);
        rot_rx<1>(sr, si, c, s);
    }

    #pragma unroll
    for (int r = 0; r < 7; r++) {
        rot_rx<8>(sr, si, gc[3 * r],     gs[3 * r]);
        rot_ry<4>(sr, si, gc[3 * r + 1], gs[3 * r + 1]);
        rot_rz<2>(sr, si, gc[3 * r + 2], gs[3 * r + 2]);
        cnot_c3_t0(sr, si);
    }
    rot_rx<8>(sr, si, gc[21], gs[21]);
    rot_ry<4>(sr, si, gc[22], gs[22]);

    float p[16];
    #pragma unroll
    for (int k = 0; k < 16; k++) p[k] = sr[k] * sr[k] + si[k] * si[k];
    #pragma unroll
    for (int w = 0; w < 4; w++) {
        int str = 8 >> w;
        float acc = 0.0f;
        #pragma unroll
        for (int k = 0; k < 16; k++) acc += (k & str) ? -p[k] : p[k];
        out[b * 4 + w] = acc;
    }
}

// ---------------------------------------------------------------------------
// Launch
// ---------------------------------------------------------------------------
extern "C" void kernel_launch(void* const* d_in, const int* in_sizes, int n_in,
                              void* d_out, int out_size) {
    const float* x       = (const float*)d_in[0];
    const float* conv1_w = (const float*)d_in[1];
    const float* conv1_b = (const float*)d_in[2];
    const float* conv2_w = (const float*)d_in[3];
    const float* conv2_b = (const float*)d_in[4];
    const float* fc1_w   = (const float*)d_in[5];
    const float* fc1_b   = (const float*)d_in[6];
    const float* fc2_w   = (const float*)d_in[7];
    const float* fc2_b   = (const float*)d_in[8];
    const float* bn_g    = (const float*)d_in[9];
    const float* bn_b    = (const float*)d_in[10];
    const float* rl      = (const float*)d_in[11];
    float* out = (float*)d_out;

    k_conv<<<BATCH / 2, 224>>>(x, conv1_w, conv1_b, conv2_w, conv2_b);
    k_fc<<<BATCH / 64, 256>>>(fc1_w, fc1_b, fc2_w, fc2_b);
    k_stats<<<1, 256>>>(bn_g, bn_b);
    k_quantum<<<BATCH / 64, 64>>>(rl, out);
}